// round 15
// baseline (speedup 1.0000x reference)
#include <cuda_runtime.h>
#include <stdint.h>

#define THREADS   256
#define GRID      2368
#define WARPS_PB  (THREADS / 32)
#define WBUF      704u                       /* pass1 per-warp staging entries */
#define FLUSH_AT  448u                       /* headroom 256 = 8 words/lane/iter */
#define KGRID     148                        /* ksel: one block per SM, co-resident */
#define KTHREADS  1024
#define KWARPS    (KTHREADS / 32)
#define WBUF2     256u                       /* ksel per-warp staging */
#define CAND_CAP  (16u * 1024u * 1024u)      /* 64 MB candidate buffer (raw words) */
#define C2_CAP    (4u * 1024u * 1024u)       /* 16 MB bin-B buffer (masked) */
#define CUTBITS   0x40000000u                /* bit pattern of 2.0f */

__device__ unsigned           g_hist1[1024];      // coarse bins u>>20 in [1024,2048)
__device__ unsigned           g_mid[2048];        // bits [19:9] within coarse bin
__device__ unsigned           g_fb[1u << 20];     // fallback-only scratch (self-zeroed)
__device__ unsigned           g_cand[CAND_CAP];   // RAW candidate/zero words
__device__ unsigned           g_c2[C2_CAP];       // masked entries in target coarse bin
__device__ unsigned           g_cur;              // candidate cursor
__device__ unsigned           g_cur2;             // bin-B cursor
__device__ unsigned long long g_zeros;
__device__ int                g_need;             // (fbk path)
__device__ int                g_ovf;              // candidate buffer overflow
__device__ int                g_ovf2;             // bin-B buffer overflow
__device__ long long          g_idx;
__device__ float              g_th;
__device__ float              g_step;
__device__ unsigned           g_gen = 0u;         // grid-barrier generation
__device__ unsigned           g_cnt = 0u;         // grid-barrier arrivals

// ---------------- software grid barrier (KGRID co-resident blocks)
__device__ __forceinline__ void gbar() {
    __syncthreads();
    if (threadIdx.x == 0) {
        unsigned gen = *((volatile unsigned*)&g_gen);
        __threadfence();
        if (atomicAdd(&g_cnt, 1u) == KGRID - 1u) {
            atomicExch(&g_cnt, 0u);
            __threadfence();
            atomicAdd(&g_gen, 1u);
        } else {
            while (*((volatile unsigned*)&g_gen) == gen) { }
        }
        __threadfence();
    }
    __syncthreads();
}

// ---------------- shuffle-based inclusive scan over 1024 threads (race-safe reuse)
__device__ unsigned block_scan_1024(unsigned v, int t, unsigned* total) {
    __shared__ unsigned wt[32];
    unsigned s = v;
    for (int o = 1; o < 32; o <<= 1) {
        unsigned u = __shfl_up_sync(0xffffffffu, s, o);
        if ((t & 31) >= o) s += u;
    }
    if ((t & 31) == 31) wt[t >> 5] = s;
    __syncthreads();
    if (t < 32) {
        unsigned w = wt[t];
        for (int o = 1; o < 32; o <<= 1) {
            unsigned u = __shfl_up_sync(0xffffffffu, w, o);
            if (t >= o) w += u;
        }
        wt[t] = w;
    }
    __syncthreads();
    if (t >= 32) s += wt[(t >> 5) - 1];
    *total = wt[31];
    __syncthreads();
    return s;
}

// ---------------- warp staging flush -> g_cand (pass1 mid-stream, rare)
__device__ __forceinline__ void warp_flush(unsigned* __restrict__ buf,
                                           unsigned* scnt_w, int lane) {
    unsigned c = *scnt_w;
    unsigned base = 0u;
    if (lane == 0) base = atomicAdd(&g_cur, c);
    base = __shfl_sync(0xffffffffu, base, 0);
    if (base + c <= CAND_CAP) {
        for (unsigned j = lane; j < c; j += 32u) g_cand[base + j] = buf[j];
    } else if (lane == 0) {
        g_ovf = 1;
    }
    __syncwarp();
    if (lane == 0) *scnt_w = 0u;
    __syncwarp();
}

// ---------------- warp staging flush -> g_c2 (ksel mid phase)
__device__ __forceinline__ void warp_flush2(unsigned* __restrict__ buf,
                                            unsigned* scnt_w, int lane) {
    unsigned c = *scnt_w;
    unsigned base = 0u;
    if (lane == 0) base = atomicAdd(&g_cur2, c);
    base = __shfl_sync(0xffffffffu, base, 0);
    if (base + c <= C2_CAP) {
        for (unsigned j = lane; j < c; j += 32u) g_c2[base + j] = buf[j];
    } else if (lane == 0) {
        g_ovf2 = 1;
    }
    __syncwarp();
    if (lane == 0) *scnt_w = 0u;
    __syncwarp();
}

// ---------------- Pass 1: pure compaction (raw words; zeros included) — verbatim
__global__ void __launch_bounds__(THREADS, 8) pass1(const uint4* __restrict__ x4,
                                                    int n4a /* mult of 64 */, int n) {
    __shared__ unsigned sbuf[WARPS_PB][WBUF];
    __shared__ unsigned scnt[WARPS_PB];
    __shared__ unsigned soff[WARPS_PB];
    __shared__ unsigned sbase;
    __shared__ int      sskip;
    int tid = threadIdx.x, lane = tid & 31, warp = tid >> 5;
    if (tid < WARPS_PB) scnt[tid] = 0u;
    __syncthreads();
    unsigned* buf = sbuf[warp];
    unsigned* cnt = &scnt[warp];

    // rare (~4.6%): |x| >= 2.0, inf, nan, or +-0.0  ->  store RAW word
#define P1_PROC(r) do { \
        if ((int)((r) << 1) <= 0) { \
            unsigned p = atomicAdd(cnt, 1u); \
            buf[p] = (r); \
        } \
    } while (0)

    for (int base = blockIdx.x * (THREADS * 2) + warp * 64; base < n4a;
         base += GRID * (THREADS * 2)) {
        __syncwarp();
        if (*cnt >= FLUSH_AT) warp_flush(buf, cnt, lane);   // warp-uniform, rare
        uint4 a = __ldcs(&x4[base + lane]);
        uint4 b = __ldcs(&x4[base + 32 + lane]);
        P1_PROC(a.x); P1_PROC(a.y); P1_PROC(a.z); P1_PROC(a.w);
        P1_PROC(b.x); P1_PROC(b.y); P1_PROC(b.z); P1_PROC(b.w);
    }
    // tail: elements [n4a*4, n), block 0 warp 0 (< 260 elements)
    if (blockIdx.x == 0 && warp == 0) {
        const unsigned* xs = (const unsigned*)x4;
        for (int i = (n4a << 2) + lane; i < n; i += 32) {
            __syncwarp();
            if (*cnt >= FLUSH_AT) warp_flush(buf, cnt, lane);
            unsigned r = xs[i];
            P1_PROC(r);
        }
    }
#undef P1_PROC

    // ---- block-level final drain: ONE global cursor atomic per block
    __syncthreads();
    if (tid == 0) {
        unsigned tot = 0u;
        for (int w = 0; w < WARPS_PB; w++) { soff[w] = tot; tot += scnt[w]; }
        unsigned base = 0u;
        if (tot) base = atomicAdd(&g_cur, tot);
        sbase = base;
        sskip = (base + tot > CAND_CAP) ? 1 : 0;
        if (base + tot > CAND_CAP) g_ovf = 1;
    }
    __syncthreads();
    if (!sskip) {
        unsigned c = scnt[warp];
        unsigned dst = sbase + soff[warp];
        for (unsigned j = lane; j < c; j += 32u) g_cand[dst + j] = buf[j];
    }
}

// ---------------- fallback (single block of ksel, exact, only if th < 2.0)
__device__ __noinline__ void fbk_device(const uint4* __restrict__ x4, int n4, int n,
                                        unsigned* sh /* [2048] */) {
    __shared__ int sbin, sch;
    __shared__ long long srank, sr3;
    int t = threadIdx.x;                 // 1024 threads
    sh[t] = 0u; sh[t + 1024] = 0u;
    __syncthreads();
    int rem = n - (n4 << 2);
    for (int i = t; i < n4; i += 1024) {
        uint4 v = x4[i];
        atomicAdd(&sh[(v.x & 0x7fffffffu) >> 20], 1u);
        atomicAdd(&sh[(v.y & 0x7fffffffu) >> 20], 1u);
        atomicAdd(&sh[(v.z & 0x7fffffffu) >> 20], 1u);
        atomicAdd(&sh[(v.w & 0x7fffffffu) >> 20], 1u);
    }
    if (t < rem) atomicAdd(&sh[(((const unsigned*)x4)[(n4 << 2) + t] & 0x7fffffffu) >> 20], 1u);
    __syncthreads();
    unsigned tot;
    unsigned c0 = sh[2 * t], c1 = sh[2 * t + 1];
    unsigned incl = block_scan_1024(c0 + c1, t, &tot);
    long long r = g_idx;
    long long inclL = (long long)incl, exclL = inclL - (long long)(c0 + c1);
    if (r >= exclL && r < inclL) {
        if (r < exclL + (long long)c0) { sbin = 2 * t;     srank = r - exclL; }
        else                           { sbin = 2 * t + 1; srank = r - exclL - (long long)c0; }
    }
    __syncthreads();
    unsigned cb = (unsigned)sbin;
    long long r2 = srank;
    for (unsigned i = t; i < (1u << 20); i += 1024u) g_fb[i] = 0u;
    __syncthreads();
    for (int i = t; i < n4; i += 1024) {
        uint4 v = x4[i];
#define FB(r_) do { unsigned u = (r_) & 0x7fffffffu; \
        if ((u >> 20) == cb) atomicAdd(&g_fb[u & 0xFFFFFu], 1u); } while (0)
        FB(v.x); FB(v.y); FB(v.z); FB(v.w);
    }
    if (t < rem) { FB(((const unsigned*)x4)[(n4 << 2) + t]); }
#undef FB
    __syncthreads();
    unsigned s = 0u;
    for (int j = 0; j < 1024; j++) s += g_fb[t * 1024 + j];
    unsigned incl3 = block_scan_1024(s, t, &tot);
    long long incl3L = (long long)incl3, excl3L = incl3L - (long long)s;
    if (r2 >= excl3L && r2 < incl3L) { sch = t; sr3 = r2 - excl3L; }
    __syncthreads();
    int ch = sch;
    long long r3 = sr3;
    unsigned c4 = g_fb[(unsigned)ch * 1024u + (unsigned)t];
    unsigned incl4 = block_scan_1024(c4, t, &tot);
    long long incl4L = (long long)incl4, excl4L = incl4L - (long long)c4;
    if (r3 >= excl4L && r3 < incl4L) {
        unsigned bits = (cb << 20) | ((unsigned)ch * 1024u + (unsigned)t);
        float th = __uint_as_float(bits);
        g_th = th;
        g_step = th / 7.0f;
    }
}

// ---------------- ksel: 2 grid barriers; block 0 finishes D/E/F solo
__global__ void __launch_bounds__(KTHREADS, 1) ksel(const uint4* __restrict__ x4,
                                                    int n4, int n, long long nll) {
    __shared__ unsigned s_hist[2048];               // mid / low / fbk (reused)
    __shared__ unsigned hrep[4096];                 // 4-replica coarse hist, bin-major
    __shared__ unsigned sbuf[KWARPS][WBUF2];
    __shared__ unsigned scnt[KWARPS];
    __shared__ int      sNeed, sB20;
    __shared__ long long sRank;
    int tid = threadIdx.x, lane = tid & 31, warp = tid >> 5;
    int ovf = *((volatile int*)&g_ovf);

    // ---- Phase A (all blocks): coarse hist + zero count; bin-major 4-replica
    for (int i = tid; i < 4096; i += KTHREADS) hrep[i] = 0u;
    __syncthreads();
    {
        unsigned rep = (unsigned)(lane & 3);
        unsigned zc = 0u;
#define PA(r_) do { unsigned u = (r_) & 0x7fffffffu; \
        if (u == 0u) { zc += 1u; } \
        else atomicAdd(&hrep[(((u >> 20) - 1024u) << 2) + rep], 1u); \
    } while (0)
        if (!ovf) {
            unsigned tot = *((volatile unsigned*)&g_cur);
            unsigned tot4 = tot >> 2;
            const uint4* c4 = (const uint4*)g_cand;
            unsigned totW = KGRID * KWARPS;
            unsigned gw = blockIdx.x * KWARPS + warp;
            for (unsigned base = gw * 32u; base < tot4; base += totW * 32u) {
                unsigned i = base + lane;
                if (i < tot4) {
                    uint4 v = c4[i];
                    PA(v.x); PA(v.y); PA(v.z); PA(v.w);
                }
            }
            if (blockIdx.x == 0 && warp == 0) {      // tail words (< 4)
                unsigned i = (tot4 << 2) + lane;
                if (i < tot) { PA(g_cand[i]); }
            }
        } else {
            unsigned totW = KGRID * KWARPS;
            unsigned gw = blockIdx.x * KWARPS + warp;
            for (int base = (int)gw * 32; base < n4; base += (int)totW * 32) {
                int i = base + lane;
                if (i < n4) {
                    uint4 v = x4[i];
#define PAX(r_) do { unsigned u = (r_) & 0x7fffffffu; \
        if (u == 0u) zc += 1u; \
        else if (u >= CUTBITS) \
            atomicAdd(&hrep[(((u >> 20) - 1024u) << 2) + rep], 1u); \
    } while (0)
                    PAX(v.x); PAX(v.y); PAX(v.z); PAX(v.w);
                }
            }
            if (blockIdx.x == 0 && warp == 0) {
                int i = (n4 << 2) + lane;
                if (i < n) { PAX(((const unsigned*)x4)[i]); }
            }
#undef PAX
        }
#undef PA
        for (int o = 16; o; o >>= 1) zc += __shfl_down_sync(0xffffffffu, zc, o);
        if (lane == 0 && zc) atomicAdd(&g_zeros, (unsigned long long)zc);
        __syncthreads();
        {
            unsigned b = (unsigned)tid;   // KTHREADS == 1024 == bins
            unsigned s = hrep[4 * b] + hrep[4 * b + 1] + hrep[4 * b + 2] + hrep[4 * b + 3];
            if (s) atomicAdd(&g_hist1[b], s);
        }
    }
    gbar();   // barrier 1 of 2

    // ---- Phase B (REPLICATED in every block): idx + coarse bin + rank
    {
        unsigned c = g_hist1[tid];
        unsigned candTot;
        unsigned incl = block_scan_1024(c, tid, &candTot);
        long long zeros = (long long)g_zeros;
        long long below = nll - (long long)candTot;  // |x| < 2.0 (incl zeros)
        long long nnz = nll - zeros;
        long long idx = (long long)floorf(0.997f * (float)nnz) + (nll - nnz);
        if (idx > nll - 1) idx = nll - 1;
        if (idx < 0) idx = 0;
        int need = (below > idx) ? 1 : 0;
        if (tid == 0) {
            sNeed = need;
            if (blockIdx.x == 0) g_idx = idx;   // for fbk
        }
        if (!need) {
            long long r = idx - below;
            long long inclL = (long long)incl;
            long long exclL = inclL - (long long)c;
            if (r >= exclL && r < inclL) { sB20 = 1024 + tid; sRank = r - exclL; }
        }
        __syncthreads();
    }
    if (sNeed) {
        if (blockIdx.x == 0) fbk_device(x4, n4, n, s_hist);
        return;   // all blocks: no further barriers on this path
    }

    // ---- Phase C (all blocks): mid hist (bits [19:9] of bin B) + bin-B compaction
    for (int i = tid; i < 2048; i += KTHREADS) s_hist[i] = 0u;
    if (lane == 0) scnt[warp] = 0u;
    __syncthreads();
    {
        unsigned B = (unsigned)sB20;
        unsigned* buf = sbuf[warp];
        unsigned* cnt = &scnt[warp];
#define P2M(rr) do { \
            unsigned u = (rr) & 0x7fffffffu; \
            if ((u >> 20) == B) {                   /* rare (~4%) */ \
                atomicAdd(&s_hist[(u >> 9) & 0x7FFu], 1u); \
                unsigned p = atomicAdd(cnt, 1u); \
                buf[p] = u; \
            } \
        } while (0)
        if (!ovf) {
            unsigned tot = *((volatile unsigned*)&g_cur);
            unsigned tot4 = tot >> 2;
            const uint4* c4 = (const uint4*)g_cand;
            unsigned totW = KGRID * KWARPS;
            unsigned gw = blockIdx.x * KWARPS + warp;
            for (unsigned base = gw * 32u; base < tot4; base += totW * 32u) {
                __syncwarp();
                if (*cnt >= WBUF2 - 128u) warp_flush2(buf, cnt, lane);
                unsigned i = base + lane;
                uint4 v = (i < tot4) ? c4[i] : make_uint4(0u, 0u, 0u, 0u);
                P2M(v.x); P2M(v.y); P2M(v.z); P2M(v.w);
            }
            if (blockIdx.x == 0 && warp == 0) {      // tail words (< 4)
                __syncwarp();
                if (*cnt >= WBUF2 - 32u) warp_flush2(buf, cnt, lane);
                unsigned i = (tot4 << 2) + lane;
                if (i < tot) { P2M(g_cand[i]); }
            }
        } else {
            unsigned totW = KGRID * KWARPS;
            unsigned gw = blockIdx.x * KWARPS + warp;
            for (int base = (int)gw * 32; base < n4; base += (int)totW * 32) {
                __syncwarp();
                if (*cnt >= WBUF2 - 128u) warp_flush2(buf, cnt, lane);
                int i = base + lane;
                uint4 v = (i < n4) ? x4[i] : make_uint4(0u, 0u, 0u, 0u);
                P2M(v.x); P2M(v.y); P2M(v.z); P2M(v.w);
            }
            if (blockIdx.x == 0 && warp == 0) {
                __syncwarp();
                if (*cnt >= WBUF2 - 32u) warp_flush2(buf, cnt, lane);
                int i = (n4 << 2) + lane;
                if (i < n) { P2M(((const unsigned*)x4)[i]); }
            }
        }
#undef P2M
        __syncwarp();
        warp_flush2(buf, cnt, lane);   // final drain
        __syncthreads();
        for (int b = tid; b < 2048; b += KTHREADS) {
            unsigned s = s_hist[b];
            if (s) atomicAdd(&g_mid[b], s);
        }
    }
    gbar();   // barrier 2 of 2
    if (blockIdx.x != 0) return;   // block 0 finishes solo

    // ---- Phase D (block 0): locate mid bin -> T21, rank2
    unsigned T21; long long r2;
    {
        __shared__ unsigned shT21;
        __shared__ long long shR2;
        unsigned tot;
        unsigned c0 = g_mid[2 * tid], c1 = g_mid[2 * tid + 1];
        unsigned incl = block_scan_1024(c0 + c1, tid, &tot);
        long long r = sRank;
        long long inclL = (long long)incl, exclL = inclL - (long long)(c0 + c1);
        if (r >= exclL && r < inclL) {
            unsigned m = (r < exclL + (long long)c0) ? (2u * (unsigned)tid)
                                                     : (2u * (unsigned)tid + 1u);
            shT21 = ((unsigned)sB20 << 11) | m;
            shR2 = (m & 1u) ? (r - exclL - (long long)c0) : (r - exclL);
        }
        __syncthreads();
        T21 = shT21;
        r2 = shR2;
    }

    // ---- Phase E (block 0): low hist (bits [8:0]) over g_c2 into SHARED
    for (int i = tid; i < 512; i += KTHREADS) s_hist[i] = 0u;
    __syncthreads();
    {
        int ovf2 = *((volatile int*)&g_ovf2);
        if (!ovf2) {
            unsigned tot = *((volatile unsigned*)&g_cur2);
            for (unsigned i = (unsigned)tid; i < tot; i += KTHREADS) {
                unsigned u = g_c2[i];       // already masked
                if ((u >> 9) == T21) atomicAdd(&s_hist[u & 0x1FFu], 1u);
            }
        } else if (!ovf) {
            unsigned tot = *((volatile unsigned*)&g_cur);
            for (unsigned i = (unsigned)tid; i < tot; i += KTHREADS) {
                unsigned u = g_cand[i] & 0x7fffffffu;
                if ((u >> 9) == T21) atomicAdd(&s_hist[u & 0x1FFu], 1u);
            }
        } else {
            for (int i = tid; i < n4; i += KTHREADS) {
                uint4 v = x4[i];
#define PL(r_) do { unsigned u = (r_) & 0x7fffffffu; \
        if ((u >> 9) == T21) atomicAdd(&s_hist[u & 0x1FFu], 1u); } while (0)
                PL(v.x); PL(v.y); PL(v.z); PL(v.w);
            }
            int rem = n - (n4 << 2);
            if (tid < rem) { PL(((const unsigned*)x4)[(n4 << 2) + tid]); }
#undef PL
        }
        __syncthreads();
    }

    // ---- Phase F (block 0): final 9 bits -> th, step
    {
        unsigned tot;
        unsigned c = (tid < 512) ? s_hist[tid] : 0u;
        unsigned incl = block_scan_1024(c, tid, &tot);
        long long inclL = (long long)incl, exclL = inclL - (long long)c;
        if (tid < 512 && r2 >= exclL && r2 < inclL) {
            unsigned bits = (T21 << 9) | (unsigned)tid;
            float th = __uint_as_float(bits);
            g_th = th;
            g_step = th / 7.0f;   // n_lv_pos = 2^(4-1)-1 = 7
        }
    }
}

// ---------------- Pass 3: quantize, warp-contiguous 4x loads + tiny state reset
__device__ __forceinline__ float quant1(float v, float th, float step) {
    if (fabsf(v) <= th) return rintf(v / step) * step;  // round-half-even (matches XLA)
    return v;
}

__device__ __forceinline__ float4 quant4(float4 v, float th, float step) {
    v.x = quant1(v.x, th, step); v.y = quant1(v.y, th, step);
    v.z = quant1(v.z, th, step); v.w = quant1(v.w, th, step);
    return v;
}

__global__ void __launch_bounds__(THREADS, 8) pass3(const float4* __restrict__ x4,
                                                    float4* __restrict__ o4,
                                                    int n4b /* mult of 128 */,
                                                    int n4, int n) {
    int tid = threadIdx.x, lane = tid & 31, warp = tid >> 5;
    float th = g_th;
    float step = g_step;
    if (th > 0.0f) {
        // each warp: 128 consecutive float4s (4 back-to-back contiguous LDG.128)
        for (int base = blockIdx.x * (THREADS * 4) + warp * 128; base < n4b;
             base += GRID * (THREADS * 4)) {
            int i = base + lane;
            float4 a = __ldcs(&x4[i]);
            float4 b = __ldcs(&x4[i + 32]);
            float4 c = __ldcs(&x4[i + 64]);
            float4 d = __ldcs(&x4[i + 96]);
            a = quant4(a, th, step); b = quant4(b, th, step);
            c = quant4(c, th, step); d = quant4(d, th, step);
            __stcs(&o4[i], a);
            __stcs(&o4[i + 32], b);
            __stcs(&o4[i + 64], c);
            __stcs(&o4[i + 96], d);
        }
        if (blockIdx.x == 0) {
            for (int i = n4b + tid; i < n4; i += THREADS) {
                float4 a = __ldcs(&x4[i]);
                __stcs(&o4[i], quant4(a, th, step));
            }
            int rem = n - (n4 << 2);
            if (tid < rem) {
                int j = (n4 << 2) + tid;
                ((float*)o4)[j] = quant1(((const float*)x4)[j], th, step);
            }
        }
    } else {
        for (int base = blockIdx.x * (THREADS * 4) + warp * 128; base < n4b;
             base += GRID * (THREADS * 4)) {
            int i = base + lane;
            float4 a = __ldcs(&x4[i]);
            float4 b = __ldcs(&x4[i + 32]);
            float4 c = __ldcs(&x4[i + 64]);
            float4 d = __ldcs(&x4[i + 96]);
            __stcs(&o4[i], a);
            __stcs(&o4[i + 32], b);
            __stcs(&o4[i + 64], c);
            __stcs(&o4[i + 96], d);
        }
        if (blockIdx.x == 0) {
            for (int i = n4b + tid; i < n4; i += THREADS) __stcs(&o4[i], __ldcs(&x4[i]));
            int rem = n - (n4 << 2);
            if (tid < rem) {
                int j = (n4 << 2) + tid;
                ((float*)o4)[j] = ((const float*)x4)[j];
            }
        }
    }
    // ---- reset tiny device state for next graph replay
    if (blockIdx.x == 0) {
        for (int b = tid; b < 1024; b += THREADS) g_hist1[b] = 0u;
        for (int b = tid; b < 2048; b += THREADS) g_mid[b] = 0u;
        if (tid == 0) {
            g_zeros = 0ull; g_cur = 0u; g_cur2 = 0u;
            g_need = 0; g_ovf = 0; g_ovf2 = 0;
        }
    }
}

extern "C" void kernel_launch(void* const* d_in, const int* in_sizes, int n_in,
                              void* d_out, int out_size) {
    const float* x = (const float*)d_in[0];
    int n = in_sizes[0];
    int n4 = n >> 2;
    int n4a = n4 & ~63;    // 64-aligned uint4 count (pass1: 2 warp-wide loads/iter)
    int n4b = n4 & ~127;   // 128-aligned float4 count (pass3: 4 warp-wide loads/iter)

    pass1<<<GRID, THREADS>>>((const uint4*)x, n4a, n);
    ksel<<<KGRID, KTHREADS>>>((const uint4*)x, n4, n, (long long)n);
    pass3<<<GRID, THREADS>>>((const float4*)x, (float4*)d_out, n4b, n4, n);
}

// round 16
// speedup vs baseline: 1.0569x; 1.0569x over previous
#include <cuda_runtime.h>
#include <stdint.h>

#define THREADS   256
#define GRID      2368
#define WARPS_PB  (THREADS / 32)
#define WBUF      704u                       /* pass1 per-warp staging entries */
#define FLUSH_AT  448u                       /* headroom 256 = 8 words/lane/iter */
#define KGRID     148                        /* ksel: one block per SM, co-resident */
#define KTHREADS  1024
#define KWARPS    (KTHREADS / 32)
#define WBUF2     512u                       /* ksel per-warp staging */
#define FLUSH2_AT 256u                       /* headroom 256 = 8 words/lane/iter */
#define CAND_CAP  (16u * 1024u * 1024u)      /* 64 MB candidate buffer (raw words) */
#define C2_CAP    (4u * 1024u * 1024u)       /* 16 MB bin-B buffer (masked) */
#define CUTBITS   0x40000000u                /* bit pattern of 2.0f */

__device__ unsigned           g_hist1[1024];      // coarse bins u>>20 in [1024,2048)
__device__ unsigned           g_mid[2048];        // bits [19:9] within coarse bin
__device__ unsigned           g_low[512];         // bits [8:0] within mid bin
__device__ unsigned           g_fb[1u << 20];     // fallback-only scratch (self-zeroed)
__device__ unsigned           g_cand[CAND_CAP];   // RAW candidate/zero words
__device__ unsigned           g_c2[C2_CAP];       // masked entries in target coarse bin
__device__ unsigned           g_cur;              // candidate cursor
__device__ unsigned           g_cur2;             // bin-B cursor
__device__ unsigned long long g_zeros;
__device__ int                g_need;             // (fbk path)
__device__ int                g_ovf;              // candidate buffer overflow
__device__ int                g_ovf2;             // bin-B buffer overflow
__device__ long long          g_idx;
__device__ float              g_th;
__device__ float              g_step;
__device__ unsigned           g_gen = 0u;         // grid-barrier generation
__device__ unsigned           g_cnt = 0u;         // grid-barrier arrivals

// ---------------- software grid barrier (KGRID co-resident blocks)
__device__ __forceinline__ void gbar() {
    __syncthreads();
    if (threadIdx.x == 0) {
        unsigned gen = *((volatile unsigned*)&g_gen);
        __threadfence();
        if (atomicAdd(&g_cnt, 1u) == KGRID - 1u) {
            atomicExch(&g_cnt, 0u);
            __threadfence();
            atomicAdd(&g_gen, 1u);
        } else {
            while (*((volatile unsigned*)&g_gen) == gen) { }
        }
        __threadfence();
    }
    __syncthreads();
}

// ---------------- shuffle-based inclusive scan over 1024 threads (race-safe reuse)
__device__ unsigned block_scan_1024(unsigned v, int t, unsigned* total) {
    __shared__ unsigned wt[32];
    unsigned s = v;
    for (int o = 1; o < 32; o <<= 1) {
        unsigned u = __shfl_up_sync(0xffffffffu, s, o);
        if ((t & 31) >= o) s += u;
    }
    if ((t & 31) == 31) wt[t >> 5] = s;
    __syncthreads();
    if (t < 32) {
        unsigned w = wt[t];
        for (int o = 1; o < 32; o <<= 1) {
            unsigned u = __shfl_up_sync(0xffffffffu, w, o);
            if (t >= o) w += u;
        }
        wt[t] = w;
    }
    __syncthreads();
    if (t >= 32) s += wt[(t >> 5) - 1];
    *total = wt[31];
    __syncthreads();
    return s;
}

// ---------------- warp staging flush -> g_cand (pass1 mid-stream, rare)
__device__ __forceinline__ void warp_flush(unsigned* __restrict__ buf,
                                           unsigned* scnt_w, int lane) {
    unsigned c = *scnt_w;
    unsigned base = 0u;
    if (lane == 0) base = atomicAdd(&g_cur, c);
    base = __shfl_sync(0xffffffffu, base, 0);
    if (base + c <= CAND_CAP) {
        for (unsigned j = lane; j < c; j += 32u) g_cand[base + j] = buf[j];
    } else if (lane == 0) {
        g_ovf = 1;
    }
    __syncwarp();
    if (lane == 0) *scnt_w = 0u;
    __syncwarp();
}

// ---------------- warp staging flush -> g_c2 (ksel mid phase)
__device__ __forceinline__ void warp_flush2(unsigned* __restrict__ buf,
                                            unsigned* scnt_w, int lane) {
    unsigned c = *scnt_w;
    unsigned base = 0u;
    if (lane == 0) base = atomicAdd(&g_cur2, c);
    base = __shfl_sync(0xffffffffu, base, 0);
    if (base + c <= C2_CAP) {
        for (unsigned j = lane; j < c; j += 32u) g_c2[base + j] = buf[j];
    } else if (lane == 0) {
        g_ovf2 = 1;
    }
    __syncwarp();
    if (lane == 0) *scnt_w = 0u;
    __syncwarp();
}

// ---------------- Pass 1: pure compaction (raw words; zeros included) — verbatim
__global__ void __launch_bounds__(THREADS, 8) pass1(const uint4* __restrict__ x4,
                                                    int n4a /* mult of 64 */, int n) {
    __shared__ unsigned sbuf[WARPS_PB][WBUF];
    __shared__ unsigned scnt[WARPS_PB];
    __shared__ unsigned soff[WARPS_PB];
    __shared__ unsigned sbase;
    __shared__ int      sskip;
    int tid = threadIdx.x, lane = tid & 31, warp = tid >> 5;
    if (tid < WARPS_PB) scnt[tid] = 0u;
    __syncthreads();
    unsigned* buf = sbuf[warp];
    unsigned* cnt = &scnt[warp];

    // rare (~4.6%): |x| >= 2.0, inf, nan, or +-0.0  ->  store RAW word
#define P1_PROC(r) do { \
        if ((int)((r) << 1) <= 0) { \
            unsigned p = atomicAdd(cnt, 1u); \
            buf[p] = (r); \
        } \
    } while (0)

    for (int base = blockIdx.x * (THREADS * 2) + warp * 64; base < n4a;
         base += GRID * (THREADS * 2)) {
        __syncwarp();
        if (*cnt >= FLUSH_AT) warp_flush(buf, cnt, lane);   // warp-uniform, rare
        uint4 a = __ldcs(&x4[base + lane]);
        uint4 b = __ldcs(&x4[base + 32 + lane]);
        P1_PROC(a.x); P1_PROC(a.y); P1_PROC(a.z); P1_PROC(a.w);
        P1_PROC(b.x); P1_PROC(b.y); P1_PROC(b.z); P1_PROC(b.w);
    }
    // tail: elements [n4a*4, n), block 0 warp 0 (< 260 elements)
    if (blockIdx.x == 0 && warp == 0) {
        const unsigned* xs = (const unsigned*)x4;
        for (int i = (n4a << 2) + lane; i < n; i += 32) {
            __syncwarp();
            if (*cnt >= FLUSH_AT) warp_flush(buf, cnt, lane);
            unsigned r = xs[i];
            P1_PROC(r);
        }
    }
#undef P1_PROC

    // ---- block-level final drain: ONE global cursor atomic per block
    __syncthreads();
    if (tid == 0) {
        unsigned tot = 0u;
        for (int w = 0; w < WARPS_PB; w++) { soff[w] = tot; tot += scnt[w]; }
        unsigned base = 0u;
        if (tot) base = atomicAdd(&g_cur, tot);
        sbase = base;
        sskip = (base + tot > CAND_CAP) ? 1 : 0;
        if (base + tot > CAND_CAP) g_ovf = 1;
    }
    __syncthreads();
    if (!sskip) {
        unsigned c = scnt[warp];
        unsigned dst = sbase + soff[warp];
        for (unsigned j = lane; j < c; j += 32u) g_cand[dst + j] = buf[j];
    }
}

// ---------------- fallback (single block of ksel, exact, only if th < 2.0)
__device__ __noinline__ void fbk_device(const uint4* __restrict__ x4, int n4, int n,
                                        unsigned* sh /* [2048] */) {
    __shared__ int sbin, sch;
    __shared__ long long srank, sr3;
    int t = threadIdx.x;                 // 1024 threads
    sh[t] = 0u; sh[t + 1024] = 0u;
    __syncthreads();
    int rem = n - (n4 << 2);
    for (int i = t; i < n4; i += 1024) {
        uint4 v = x4[i];
        atomicAdd(&sh[(v.x & 0x7fffffffu) >> 20], 1u);
        atomicAdd(&sh[(v.y & 0x7fffffffu) >> 20], 1u);
        atomicAdd(&sh[(v.z & 0x7fffffffu) >> 20], 1u);
        atomicAdd(&sh[(v.w & 0x7fffffffu) >> 20], 1u);
    }
    if (t < rem) atomicAdd(&sh[(((const unsigned*)x4)[(n4 << 2) + t] & 0x7fffffffu) >> 20], 1u);
    __syncthreads();
    unsigned tot;
    unsigned c0 = sh[2 * t], c1 = sh[2 * t + 1];
    unsigned incl = block_scan_1024(c0 + c1, t, &tot);
    long long r = g_idx;
    long long inclL = (long long)incl, exclL = inclL - (long long)(c0 + c1);
    if (r >= exclL && r < inclL) {
        if (r < exclL + (long long)c0) { sbin = 2 * t;     srank = r - exclL; }
        else                           { sbin = 2 * t + 1; srank = r - exclL - (long long)c0; }
    }
    __syncthreads();
    unsigned cb = (unsigned)sbin;
    long long r2 = srank;
    for (unsigned i = t; i < (1u << 20); i += 1024u) g_fb[i] = 0u;
    __syncthreads();
    for (int i = t; i < n4; i += 1024) {
        uint4 v = x4[i];
#define FB(r_) do { unsigned u = (r_) & 0x7fffffffu; \
        if ((u >> 20) == cb) atomicAdd(&g_fb[u & 0xFFFFFu], 1u); } while (0)
        FB(v.x); FB(v.y); FB(v.z); FB(v.w);
    }
    if (t < rem) { FB(((const unsigned*)x4)[(n4 << 2) + t]); }
#undef FB
    __syncthreads();
    unsigned s = 0u;
    for (int j = 0; j < 1024; j++) s += g_fb[t * 1024 + j];
    unsigned incl3 = block_scan_1024(s, t, &tot);
    long long incl3L = (long long)incl3, excl3L = incl3L - (long long)s;
    if (r2 >= excl3L && r2 < incl3L) { sch = t; sr3 = r2 - excl3L; }
    __syncthreads();
    int ch = sch;
    long long r3 = sr3;
    unsigned c4 = g_fb[(unsigned)ch * 1024u + (unsigned)t];
    unsigned incl4 = block_scan_1024(c4, t, &tot);
    long long incl4L = (long long)incl4, excl4L = incl4L - (long long)c4;
    if (r3 >= excl4L && r3 < incl4L) {
        unsigned bits = (cb << 20) | ((unsigned)ch * 1024u + (unsigned)t);
        float th = __uint_as_float(bits);
        g_th = th;
        g_step = th / 7.0f;
    }
}

// ---------------- ksel: replica-hist + replicated scans, 3 grid barriers (R14 shape)
__global__ void __launch_bounds__(KTHREADS, 1) ksel(const uint4* __restrict__ x4,
                                                    int n4, int n, long long nll) {
    __shared__ unsigned s_hist[2048];               // mid / low / fbk (reused)
    __shared__ unsigned hrep[4096];                 // 4-replica coarse hist, bin-major
    __shared__ unsigned sbuf[KWARPS][WBUF2];
    __shared__ unsigned scnt[KWARPS];
    __shared__ int      sNeed, sB20;
    __shared__ long long sRank;
    __shared__ unsigned sT21;
    __shared__ long long sRank2;
    int tid = threadIdx.x, lane = tid & 31, warp = tid >> 5;
    int ovf = *((volatile int*)&g_ovf);

    // ---- Phase A (all blocks): coarse hist + zero count; 8 words/lane per iter
    for (int i = tid; i < 4096; i += KTHREADS) hrep[i] = 0u;
    __syncthreads();
    {
        unsigned rep = (unsigned)(lane & 3);
        unsigned zc = 0u;
#define PA(r_) do { unsigned u = (r_) & 0x7fffffffu; \
        if (u == 0u) { zc += 1u; } \
        else atomicAdd(&hrep[(((u >> 20) - 1024u) << 2) + rep], 1u); \
    } while (0)
        if (!ovf) {
            unsigned tot = *((volatile unsigned*)&g_cur);
            unsigned tot4 = tot >> 2;
            const uint4* c4 = (const uint4*)g_cand;
            unsigned totW = KGRID * KWARPS;
            unsigned gw = blockIdx.x * KWARPS + warp;
            for (unsigned base = gw * 64u; base < tot4; base += totW * 64u) {
                unsigned i = base + lane;
                unsigned i2 = i + 32u;
                bool a1 = (i < tot4), a2 = (i2 < tot4);
                uint4 va = a1 ? c4[i] : make_uint4(1u, 1u, 1u, 1u);   // 1 -> bin 0 path? no:
                uint4 vb = a2 ? c4[i2] : make_uint4(1u, 1u, 1u, 1u);
                // guard: inactive lanes must not touch hist/zeros
                if (a1) { PA(va.x); PA(va.y); PA(va.z); PA(va.w); }
                if (a2) { PA(vb.x); PA(vb.y); PA(vb.z); PA(vb.w); }
            }
            if (blockIdx.x == 0 && warp == 0) {      // tail words (< 4)
                unsigned i = (tot4 << 2) + lane;
                if (i < tot) { PA(g_cand[i]); }
            }
        } else {
            unsigned totW = KGRID * KWARPS;
            unsigned gw = blockIdx.x * KWARPS + warp;
            for (int base = (int)gw * 32; base < n4; base += (int)totW * 32) {
                int i = base + lane;
                if (i < n4) {
                    uint4 v = x4[i];
#define PAX(r_) do { unsigned u = (r_) & 0x7fffffffu; \
        if (u == 0u) zc += 1u; \
        else if (u >= CUTBITS) \
            atomicAdd(&hrep[(((u >> 20) - 1024u) << 2) + rep], 1u); \
    } while (0)
                    PAX(v.x); PAX(v.y); PAX(v.z); PAX(v.w);
                }
            }
            if (blockIdx.x == 0 && warp == 0) {
                int i = (n4 << 2) + lane;
                if (i < n) { PAX(((const unsigned*)x4)[i]); }
            }
#undef PAX
        }
#undef PA
        for (int o = 16; o; o >>= 1) zc += __shfl_down_sync(0xffffffffu, zc, o);
        if (lane == 0 && zc) atomicAdd(&g_zeros, (unsigned long long)zc);
        __syncthreads();
        {
            unsigned b = (unsigned)tid;   // KTHREADS == 1024 == bins
            unsigned s = hrep[4 * b] + hrep[4 * b + 1] + hrep[4 * b + 2] + hrep[4 * b + 3];
            if (s) atomicAdd(&g_hist1[b], s);
        }
    }
    gbar();   // barrier 1 of 3

    // ---- Phase B (REPLICATED in every block): idx + coarse bin + rank
    {
        unsigned c = g_hist1[tid];
        unsigned candTot;
        unsigned incl = block_scan_1024(c, tid, &candTot);
        long long zeros = (long long)g_zeros;
        long long below = nll - (long long)candTot;  // |x| < 2.0 (incl zeros)
        long long nnz = nll - zeros;
        long long idx = (long long)floorf(0.997f * (float)nnz) + (nll - nnz);
        if (idx > nll - 1) idx = nll - 1;
        if (idx < 0) idx = 0;
        int need = (below > idx) ? 1 : 0;
        if (tid == 0) {
            sNeed = need;
            if (blockIdx.x == 0) g_idx = idx;   // for fbk
        }
        if (!need) {
            long long r = idx - below;
            long long inclL = (long long)incl;
            long long exclL = inclL - (long long)c;
            if (r >= exclL && r < inclL) { sB20 = 1024 + tid; sRank = r - exclL; }
        }
        __syncthreads();
    }
    if (sNeed) {
        if (blockIdx.x == 0) fbk_device(x4, n4, n, s_hist);
        return;   // all blocks: no further barriers on this path
    }

    // ---- Phase C (all blocks): mid hist + bin-B compaction; 8 words/lane per iter
    for (int i = tid; i < 2048; i += KTHREADS) s_hist[i] = 0u;
    if (lane == 0) scnt[warp] = 0u;
    __syncthreads();
    {
        unsigned B = (unsigned)sB20;
        unsigned* buf = sbuf[warp];
        unsigned* cnt = &scnt[warp];
#define P2M(rr) do { \
            unsigned u = (rr) & 0x7fffffffu; \
            if ((u >> 20) == B) {                   /* rare (~4%) */ \
                atomicAdd(&s_hist[(u >> 9) & 0x7FFu], 1u); \
                unsigned p = atomicAdd(cnt, 1u); \
                buf[p] = u; \
            } \
        } while (0)
        if (!ovf) {
            unsigned tot = *((volatile unsigned*)&g_cur);
            unsigned tot4 = tot >> 2;
            const uint4* c4 = (const uint4*)g_cand;
            unsigned totW = KGRID * KWARPS;
            unsigned gw = blockIdx.x * KWARPS + warp;
            for (unsigned base = gw * 64u; base < tot4; base += totW * 64u) {
                __syncwarp();
                if (*cnt >= FLUSH2_AT) warp_flush2(buf, cnt, lane);
                unsigned i = base + lane;
                unsigned i2 = i + 32u;
                uint4 va = (i < tot4) ? c4[i] : make_uint4(0u, 0u, 0u, 0u);
                uint4 vb = (i2 < tot4) ? c4[i2] : make_uint4(0u, 0u, 0u, 0u);
                P2M(va.x); P2M(va.y); P2M(va.z); P2M(va.w);
                P2M(vb.x); P2M(vb.y); P2M(vb.z); P2M(vb.w);
            }
            if (blockIdx.x == 0 && warp == 0) {      // tail words (< 4)
                __syncwarp();
                if (*cnt >= FLUSH2_AT) warp_flush2(buf, cnt, lane);
                unsigned i = (tot4 << 2) + lane;
                if (i < tot) { P2M(g_cand[i]); }
            }
        } else {
            unsigned totW = KGRID * KWARPS;
            unsigned gw = blockIdx.x * KWARPS + warp;
            for (int base = (int)gw * 32; base < n4; base += (int)totW * 32) {
                __syncwarp();
                if (*cnt >= FLUSH2_AT) warp_flush2(buf, cnt, lane);
                int i = base + lane;
                uint4 v = (i < n4) ? x4[i] : make_uint4(0u, 0u, 0u, 0u);
                P2M(v.x); P2M(v.y); P2M(v.z); P2M(v.w);
            }
            if (blockIdx.x == 0 && warp == 0) {
                __syncwarp();
                if (*cnt >= FLUSH2_AT) warp_flush2(buf, cnt, lane);
                int i = (n4 << 2) + lane;
                if (i < n) { P2M(((const unsigned*)x4)[i]); }
            }
        }
#undef P2M
        __syncwarp();
        warp_flush2(buf, cnt, lane);   // final drain
        __syncthreads();
        for (int b = tid; b < 2048; b += KTHREADS) {
            unsigned s = s_hist[b];
            if (s) atomicAdd(&g_mid[b], s);
        }
    }
    gbar();   // barrier 2 of 3

    // ---- Phase D (REPLICATED): locate mid bin -> sT21, sRank2
    {
        unsigned tot;
        unsigned c0 = g_mid[2 * tid], c1 = g_mid[2 * tid + 1];
        unsigned incl = block_scan_1024(c0 + c1, tid, &tot);
        long long r = sRank;
        long long inclL = (long long)incl, exclL = inclL - (long long)(c0 + c1);
        if (r >= exclL && r < inclL) {
            unsigned m = (r < exclL + (long long)c0) ? (2u * (unsigned)tid)
                                                     : (2u * (unsigned)tid + 1u);
            sT21 = ((unsigned)sB20 << 11) | m;
            sRank2 = (m & 1u) ? (r - exclL - (long long)c0) : (r - exclL);
        }
        __syncthreads();
    }

    // ---- Phase E (all blocks): low hist (bits [8:0] of mid bin)
    for (int i = tid; i < 512; i += KTHREADS) s_hist[i] = 0u;
    __syncthreads();
    {
        unsigned T21 = sT21;
        unsigned stride = KGRID * KTHREADS;
        unsigned t0 = blockIdx.x * KTHREADS + tid;
        int ovf2 = *((volatile int*)&g_ovf2);
        if (!ovf2) {
            unsigned tot = *((volatile unsigned*)&g_cur2);
            for (unsigned i = t0; i < tot; i += stride) {
                unsigned u = g_c2[i];       // already masked
                if ((u >> 9) == T21) atomicAdd(&s_hist[u & 0x1FFu], 1u);
            }
        } else if (!ovf) {
            unsigned tot = *((volatile unsigned*)&g_cur);
            for (unsigned i = t0; i < tot; i += stride) {
                unsigned u = g_cand[i] & 0x7fffffffu;
                if ((u >> 9) == T21) atomicAdd(&s_hist[u & 0x1FFu], 1u);
            }
        } else {
            for (int i = (int)t0; i < n4; i += (int)stride) {
                uint4 v = x4[i];
#define PL(r_) do { unsigned u = (r_) & 0x7fffffffu; \
        if ((u >> 9) == T21) atomicAdd(&s_hist[u & 0x1FFu], 1u); } while (0)
                PL(v.x); PL(v.y); PL(v.z); PL(v.w);
            }
            int rem = n - (n4 << 2);
            if ((int)t0 < rem) { PL(((const unsigned*)x4)[(n4 << 2) + (int)t0]); }
#undef PL
        }
        __syncthreads();
        for (int b = tid; b < 512; b += KTHREADS) {
            unsigned s = s_hist[b];
            if (s) atomicAdd(&g_low[b], s);
        }
    }
    gbar();   // barrier 3 of 3

    // ---- Phase F (block 0): final 9 bits -> th, step
    if (blockIdx.x == 0) {
        unsigned tot;
        unsigned c = (tid < 512) ? g_low[tid] : 0u;
        unsigned incl = block_scan_1024(c, tid, &tot);
        long long r = sRank2;
        long long inclL = (long long)incl, exclL = inclL - (long long)c;
        if (tid < 512 && r >= exclL && r < inclL) {
            unsigned bits = (sT21 << 9) | (unsigned)tid;
            float th = __uint_as_float(bits);
            g_th = th;
            g_step = th / 7.0f;   // n_lv_pos = 2^(4-1)-1 = 7
        }
    }
}

// ---------------- Pass 3: quantize, warp-contiguous 4x loads + tiny state reset
__device__ __forceinline__ float quant1(float v, float th, float step) {
    if (fabsf(v) <= th) return rintf(v / step) * step;  // round-half-even (matches XLA)
    return v;
}

__device__ __forceinline__ float4 quant4(float4 v, float th, float step) {
    v.x = quant1(v.x, th, step); v.y = quant1(v.y, th, step);
    v.z = quant1(v.z, th, step); v.w = quant1(v.w, th, step);
    return v;
}

__global__ void __launch_bounds__(THREADS, 8) pass3(const float4* __restrict__ x4,
                                                    float4* __restrict__ o4,
                                                    int n4b /* mult of 128 */,
                                                    int n4, int n) {
    int tid = threadIdx.x, lane = tid & 31, warp = tid >> 5;
    float th = g_th;
    float step = g_step;
    if (th > 0.0f) {
        // each warp: 128 consecutive float4s (4 back-to-back contiguous LDG.128)
        for (int base = blockIdx.x * (THREADS * 4) + warp * 128; base < n4b;
             base += GRID * (THREADS * 4)) {
            int i = base + lane;
            float4 a = __ldcs(&x4[i]);
            float4 b = __ldcs(&x4[i + 32]);
            float4 c = __ldcs(&x4[i + 64]);
            float4 d = __ldcs(&x4[i + 96]);
            a = quant4(a, th, step); b = quant4(b, th, step);
            c = quant4(c, th, step); d = quant4(d, th, step);
            __stcs(&o4[i], a);
            __stcs(&o4[i + 32], b);
            __stcs(&o4[i + 64], c);
            __stcs(&o4[i + 96], d);
        }
        if (blockIdx.x == 0) {
            for (int i = n4b + tid; i < n4; i += THREADS) {
                float4 a = __ldcs(&x4[i]);
                __stcs(&o4[i], quant4(a, th, step));
            }
            int rem = n - (n4 << 2);
            if (tid < rem) {
                int j = (n4 << 2) + tid;
                ((float*)o4)[j] = quant1(((const float*)x4)[j], th, step);
            }
        }
    } else {
        for (int base = blockIdx.x * (THREADS * 4) + warp * 128; base < n4b;
             base += GRID * (THREADS * 4)) {
            int i = base + lane;
            float4 a = __ldcs(&x4[i]);
            float4 b = __ldcs(&x4[i + 32]);
            float4 c = __ldcs(&x4[i + 64]);
            float4 d = __ldcs(&x4[i + 96]);
            __stcs(&o4[i], a);
            __stcs(&o4[i + 32], b);
            __stcs(&o4[i + 64], c);
            __stcs(&o4[i + 96], d);
        }
        if (blockIdx.x == 0) {
            for (int i = n4b + tid; i < n4; i += THREADS) __stcs(&o4[i], __ldcs(&x4[i]));
            int rem = n - (n4 << 2);
            if (tid < rem) {
                int j = (n4 << 2) + tid;
                ((float*)o4)[j] = ((const float*)x4)[j];
            }
        }
    }
    // ---- reset tiny device state for next graph replay
    if (blockIdx.x == 0) {
        for (int b = tid; b < 1024; b += THREADS) g_hist1[b] = 0u;
        for (int b = tid; b < 2048; b += THREADS) g_mid[b] = 0u;
        for (int b = tid; b < 512; b += THREADS) g_low[b] = 0u;
        if (tid == 0) {
            g_zeros = 0ull; g_cur = 0u; g_cur2 = 0u;
            g_need = 0; g_ovf = 0; g_ovf2 = 0;
        }
    }
}

extern "C" void kernel_launch(void* const* d_in, const int* in_sizes, int n_in,
                              void* d_out, int out_size) {
    const float* x = (const float*)d_in[0];
    int n = in_sizes[0];
    int n4 = n >> 2;
    int n4a = n4 & ~63;    // 64-aligned uint4 count (pass1: 2 warp-wide loads/iter)
    int n4b = n4 & ~127;   // 128-aligned float4 count (pass3: 4 warp-wide loads/iter)

    pass1<<<GRID, THREADS>>>((const uint4*)x, n4a, n);
    ksel<<<KGRID, KTHREADS>>>((const uint4*)x, n4, n, (long long)n);
    pass3<<<GRID, THREADS>>>((const float4*)x, (float4*)d_out, n4b, n4, n);
}